// round 12
// baseline (speedup 1.0000x reference)
#include <cuda_runtime.h>
#include <cuda_bf16.h>
#include <cuda_fp16.h>
#include <cstdint>

// ---------------------------------------------------------------------------
// DeformableAttention (B=8, N=4096, C=256, S=4, NH=8, NL=1, NP=4, HD=32)
//
// fp16 mma.sync pipeline v3 (4 launches):
//   1. prep: q->fp16; vmean->fp16; Wv,Wo,Wfold transposes; bias fold
//   2. vpm   = vmean @ Wv + bv            (BN=64 GEMM, fp16 out)
//   3. fused (BM=64, 512 blocks): offattn GEMM tile in smem + softmax +
//      bilinear sampling -> pre fp16
//   4. out   = pre @ Wo + bo              (BN=128 GEMM, fp32 out)
// ---------------------------------------------------------------------------

namespace {
constexpr int Bn   = 8;
constexpr int Nn   = 4096;
constexpr int Cc   = 256;   // K for all GEMMs
constexpr int NHh  = 8;
constexpr int NPp  = 4;
constexpr int HDd  = 32;
constexpr int ROWS = Bn * Nn;    // 32768
constexpr int GW   = 64;
constexpr int NF   = 128;        // padded offattn width
}

// -------------------- scratch (static device globals) ----------------------
__device__ __align__(16) __half g_q16[(size_t)ROWS * Cc];
__device__ __align__(16) __half g_vm16[Nn * Cc];
__device__ __align__(16) __half g_vpm_h[Nn * Cc];
__device__ __align__(16) float g_bfold[NF];
__device__ __align__(16) __half g_WvT[Cc * Cc];
__device__ __align__(16) __half g_WoT[Cc * Cc];
__device__ __align__(16) __half g_WfT[NF * Cc];
__device__ __align__(16) __half g_pre16[(size_t)ROWS * Cc];

// -------------------- helpers ----------------------------------------------
__device__ __forceinline__ void mma_f16(float c[4], const uint32_t a[4],
                                        const uint32_t b[2]) {
    asm volatile(
        "mma.sync.aligned.m16n8k16.row.col.f32.f16.f16.f32 "
        "{%0,%1,%2,%3}, {%4,%5,%6,%7}, {%8,%9}, {%0,%1,%2,%3};\n"
        : "+f"(c[0]), "+f"(c[1]), "+f"(c[2]), "+f"(c[3])
        : "r"(a[0]), "r"(a[1]), "r"(a[2]), "r"(a[3]), "r"(b[0]), "r"(b[1]));
}

__device__ __forceinline__ void ldmx4(uint32_t r[4], uint32_t addr) {
    asm volatile(
        "ldmatrix.sync.aligned.m8n8.x4.shared.b16 {%0,%1,%2,%3}, [%4];\n"
        : "=r"(r[0]), "=r"(r[1]), "=r"(r[2]), "=r"(r[3]) : "r"(addr));
}

__device__ __forceinline__ void cp_async16(uint32_t dst, const void* src) {
    asm volatile("cp.async.cg.shared.global [%0], [%1], 16;\n"
                 :: "r"(dst), "l"(src));
}
__device__ __forceinline__ void cp_commit() {
    asm volatile("cp.async.commit_group;\n");
}
template <int NN>
__device__ __forceinline__ void cp_wait() {
    asm volatile("cp.async.wait_group %0;\n" :: "n"(NN));
}

// -------------------- GEMM: C = A @ Bt^T + bias (fp16 operands) ------------
// BM=128, BN in {64,128}, BK=32, 3-stage cp.async, ldmatrix + XOR swizzle.
template <int BN, bool HALF_OUT>
__global__ void __launch_bounds__(256, 2)
gemm_f16(const __half* __restrict__ Ag,
         const __half* __restrict__ Bg,
         const float* __restrict__ bias, void* __restrict__ Cout,
         int M, int N) {
    constexpr int K = Cc, BM = 128, BK = 32;
    constexpr int NK = K / BK;     // 8
    constexpr int STB = 8192 + BN * 64;            // stage bytes
    constexpr int WN = BN / 2;                     // cols per warp
    constexpr int NT = WN / 8;                     // 8-col frags per warp
    __shared__ __align__(128) uint8_t smem[3 * STB];
    const uint32_t sb = (uint32_t)__cvta_generic_to_shared(smem);

    const int t = threadIdx.x, w = t >> 5, l = t & 31;
    const int wm = w & 3, wn = w >> 2;
    const int g = l >> 2, qq = l & 3;
    const int blockRow = blockIdx.y * BM;
    const int blockCol = blockIdx.x * BN;
    const int lr = t >> 2, lc = t & 3;

    float acc[2][NT][4];
#pragma unroll
    for (int i = 0; i < 2; i++)
#pragma unroll
        for (int j = 0; j < NT; j++)
#pragma unroll
            for (int x = 0; x < 4; x++) acc[i][j][x] = 0.f;

    auto stage = [&](int buf, int k0) {
        const uint32_t base = sb + buf * STB;
#pragma unroll
        for (int j = 0; j < 2; j++) {
            int row = lr + j * 64;
            uint32_t sw = (uint32_t)row * 64 + (uint32_t)((lc ^ ((row >> 1) & 3)) * 16);
            cp_async16(base + sw, Ag + (size_t)(blockRow + row) * K + k0 + lc * 8);
        }
#pragma unroll
        for (int j = 0; j < BN / 64; j++) {
            int row = lr + j * 64;
            uint32_t sw = (uint32_t)row * 64 + (uint32_t)((lc ^ ((row >> 1) & 3)) * 16);
            cp_async16(base + 8192 + sw, Bg + (size_t)(blockCol + row) * K + k0 + lc * 8);
        }
        cp_commit();
    };

    auto compute = [&](int buf) {
        const uint32_t base = sb + buf * STB;
        const int seg = l >> 3, sl = l & 7;
#pragma unroll
        for (int ks = 0; ks < 2; ks++) {
            uint32_t bF[NT][2];
#pragma unroll
            for (int nt = 0; nt < NT / 2; nt++) {
                int r = wn * WN + nt * 16 + (seg >> 1) * 8 + sl;
                int c = ks * 2 + (seg & 1);
                uint32_t addr = (uint32_t)r * 64 + (uint32_t)((c ^ ((r >> 1) & 3)) * 16);
                uint32_t tmp[4];
                ldmx4(tmp, base + 8192 + addr);
                bF[nt * 2][0] = tmp[0]; bF[nt * 2][1] = tmp[1];
                bF[nt * 2 + 1][0] = tmp[2]; bF[nt * 2 + 1][1] = tmp[3];
            }
            uint32_t aF[2][4];
#pragma unroll
            for (int mt = 0; mt < 2; mt++) {
                int r = wm * 32 + mt * 16 + (seg & 1) * 8 + sl;
                int c = ks * 2 + (seg >> 1);
                uint32_t addr = (uint32_t)r * 64 + (uint32_t)((c ^ ((r >> 1) & 3)) * 16);
                ldmx4(aF[mt], base + addr);
            }
#pragma unroll
            for (int mt = 0; mt < 2; mt++)
#pragma unroll
                for (int nf = 0; nf < NT; nf++)
                    mma_f16(acc[mt][nf], aF[mt], bF[nf]);
        }
    };

    stage(0, 0);
    stage(1, BK);
    for (int kt = 0; kt < NK; kt++) {
        if (kt + 2 < NK) cp_wait<1>();
        else             cp_wait<0>();
        __syncthreads();
        if (kt + 2 < NK) stage((kt + 2) % 3, (kt + 2) * BK);
        compute(kt % 3);
    }

    // epilogue
#pragma unroll
    for (int mt = 0; mt < 2; mt++) {
        int row = blockRow + wm * 32 + mt * 16 + g;
#pragma unroll
        for (int nf = 0; nf < NT; nf++) {
            int col = blockCol + wn * WN + nf * 8 + 2 * qq;
            float2 bb = *(const float2*)&bias[col];
            float v00 = acc[mt][nf][0] + bb.x, v01 = acc[mt][nf][1] + bb.y;
            float v10 = acc[mt][nf][2] + bb.x, v11 = acc[mt][nf][3] + bb.y;
            if (HALF_OUT) {
                __half2* Ch = (__half2*)Cout;
                Ch[((size_t)row * N + col) >> 1]       = __floats2half2_rn(v00, v01);
                Ch[((size_t)(row + 8) * N + col) >> 1] = __floats2half2_rn(v10, v11);
            } else {
                float* Cf = (float*)Cout;
                *(float2*)&Cf[(size_t)row * N + col]       = make_float2(v00, v01);
                *(float2*)&Cf[(size_t)(row + 8) * N + col] = make_float2(v10, v11);
            }
        }
    }
}

// -------------------- fused offattn GEMM + sampling (BM=64) ----------------
// One block per 64 query rows: GEMM (64 x 96 of q @ WfT, padded BN=128)
// -> offattn tile in smem -> softmax + bilinear sampling -> g_pre16.
// smem: 3 stages x 12KB (A 4K | B 8K) overlaid with 64x96 fp32 tile (24KB).
__global__ void __launch_bounds__(256, 2)
fused_offattn_sample(const __half* __restrict__ Ag,
                     const __half* __restrict__ Bg,
                     const float* __restrict__ bias) {
    constexpr int K = Cc, BM = 64, BK = 32;
    constexpr int NK = K / BK;        // 8
    constexpr int FST = 12288;        // A 4K | B 8K
    __shared__ __align__(128) uint8_t smem[3 * FST];
    const uint32_t sb = (uint32_t)__cvta_generic_to_shared(smem);
    float* s_oa = (float*)smem;       // [64][96] after GEMM

    const int t = threadIdx.x, w = t >> 5, l = t & 31;
    const int wm = w & 1, wn = w >> 1;           // 2 x 4 warp grid
    const int g = l >> 2, qq = l & 3;
    const int blockRow = blockIdx.x * BM;
    const int lr = t >> 2, lc = t & 3;

    float acc[2][4][4];
#pragma unroll
    for (int i = 0; i < 2; i++)
#pragma unroll
        for (int j = 0; j < 4; j++)
#pragma unroll
            for (int x = 0; x < 4; x++) acc[i][j][x] = 0.f;

    auto stage = [&](int buf, int k0) {
        const uint32_t base = sb + buf * FST;
        {   // A: 64 rows, 1 chunk/thread
            uint32_t sw = (uint32_t)lr * 64 + (uint32_t)((lc ^ ((lr >> 1) & 3)) * 16);
            cp_async16(base + sw, Ag + (size_t)(blockRow + lr) * K + k0 + lc * 8);
        }
#pragma unroll
        for (int j = 0; j < 2; j++) {   // B: 128 rows, 2 chunks/thread
            int row = lr + j * 64;
            uint32_t sw = (uint32_t)row * 64 + (uint32_t)((lc ^ ((row >> 1) & 3)) * 16);
            cp_async16(base + 4096 + sw, Bg + (size_t)row * K + k0 + lc * 8);
        }
        cp_commit();
    };

    auto compute = [&](int buf) {
        const uint32_t base = sb + buf * FST;
        const int seg = l >> 3, sl = l & 7;
#pragma unroll
        for (int ks = 0; ks < 2; ks++) {
            uint32_t bF[4][2];
#pragma unroll
            for (int nt = 0; nt < 2; nt++) {
                int r = wn * 32 + nt * 16 + (seg >> 1) * 8 + sl;
                int c = ks * 2 + (seg & 1);
                uint32_t addr = (uint32_t)r * 64 + (uint32_t)((c ^ ((r >> 1) & 3)) * 16);
                uint32_t tmp[4];
                ldmx4(tmp, base + 4096 + addr);
                bF[nt * 2][0] = tmp[0]; bF[nt * 2][1] = tmp[1];
                bF[nt * 2 + 1][0] = tmp[2]; bF[nt * 2 + 1][1] = tmp[3];
            }
            uint32_t aF[2][4];
#pragma unroll
            for (int mt = 0; mt < 2; mt++) {
                int r = wm * 32 + mt * 16 + (seg & 1) * 8 + sl;
                int c = ks * 2 + (seg >> 1);
                uint32_t addr = (uint32_t)r * 64 + (uint32_t)((c ^ ((r >> 1) & 3)) * 16);
                ldmx4(aF[mt], base + addr);
            }
#pragma unroll
            for (int mt = 0; mt < 2; mt++)
#pragma unroll
                for (int nf = 0; nf < 4; nf++)
                    mma_f16(acc[mt][nf], aF[mt], bF[nf]);
        }
    };

    stage(0, 0);
    stage(1, BK);
    for (int kt = 0; kt < NK; kt++) {
        if (kt + 2 < NK) cp_wait<1>();
        else             cp_wait<0>();
        __syncthreads();
        if (kt + 2 < NK) stage((kt + 2) % 3, (kt + 2) * BK);
        compute(kt % 3);
    }
    __syncthreads();   // stage buffers done; safe to overlay s_oa

    // epilogue into smem (cols >= 96 discarded)
#pragma unroll
    for (int mt = 0; mt < 2; mt++) {
        int rl = wm * 32 + mt * 16 + g;
#pragma unroll
        for (int nf = 0; nf < 4; nf++) {
            int col = wn * 32 + nf * 8 + 2 * qq;
            if (col < 96) {
                float b0 = bias[col], b1 = bias[col + 1];
                s_oa[rl * 96 + col]           = acc[mt][nf][0] + b0;
                s_oa[rl * 96 + col + 1]       = acc[mt][nf][1] + b1;
                s_oa[(rl + 8) * 96 + col]     = acc[mt][nf][2] + b0;
                s_oa[(rl + 8) * 96 + col + 1] = acc[mt][nf][3] + b1;
            }
        }
    }
    __syncthreads();

    // sampling: warp w handles rows w*8 .. w*8+7; lane = head-dim index
    const int lane = l;
    for (int rl = w * 8; rl < w * 8 + 8; rl++) {
        const int row = blockRow + rl;
        const int n = row & (Nn - 1);
        const float refx = (float)(n & (GW - 1)) * (1.0f / 63.0f);
        const float refy = (float)(n >> 6) * (1.0f / 63.0f);
        const float* oa = s_oa + rl * 96;

#pragma unroll
        for (int h = 0; h < NHh; h++) {
            float l0 = oa[64 + h * 4 + 0];
            float l1 = oa[64 + h * 4 + 1];
            float l2 = oa[64 + h * 4 + 2];
            float l3 = oa[64 + h * 4 + 3];
            float m  = fmaxf(fmaxf(l0, l1), fmaxf(l2, l3));
            float e0 = __expf(l0 - m), e1 = __expf(l1 - m);
            float e2 = __expf(l2 - m), e3 = __expf(l3 - m);
            float inv = 1.0f / (e0 + e1 + e2 + e3);
            float wp[4] = {e0 * inv, e1 * inv, e2 * inv, e3 * inv};

            const __half* fmap = g_vpm_h + h * HDd + lane;
            float acc2 = 0.f;
#pragma unroll
            for (int p = 0; p < NPp; p++) {
                float ox = oa[h * 8 + p * 2 + 0];
                float oy = oa[h * 8 + p * 2 + 1];
                float lx = fminf(fmaxf(refx + ox, 0.f), 1.f);
                float ly = fminf(fmaxf(refy + oy, 0.f), 1.f);
                float x = lx * (float)GW - 0.5f;
                float y = ly * (float)GW - 0.5f;
                float xf = floorf(x), yf = floorf(y);
                float tx = x - xf, ty = y - yf;
                int x0 = (int)xf, y0 = (int)yf;
                int x1 = x0 + 1, y1 = y0 + 1;
                bool vx0 = (x0 >= 0), vx1 = (x1 < GW);
                bool vy0 = (y0 >= 0), vy1 = (y1 < GW);
                float w00 = (1.f - tx) * (1.f - ty);
                float w01 = tx * (1.f - ty);
                float w10 = (1.f - tx) * ty;
                float w11 = tx * ty;
                float a = 0.f;
                if (vx0 && vy0) a = fmaf(w00, __half2float(fmap[(size_t)(y0 * GW + x0) * Cc]), a);
                if (vx1 && vy0) a = fmaf(w01, __half2float(fmap[(size_t)(y0 * GW + x1) * Cc]), a);
                if (vx0 && vy1) a = fmaf(w10, __half2float(fmap[(size_t)(y1 * GW + x0) * Cc]), a);
                if (vx1 && vy1) a = fmaf(w11, __half2float(fmap[(size_t)(y1 * GW + x1) * Cc]), a);
                acc2 = fmaf(wp[p], a, acc2);
            }
            g_pre16[(size_t)row * Cc + h * HDd + lane] = __float2half_rn(acc2);
        }
    }
}

// -------------------- prep: conversions + transposes + fold + bias ---------
__global__ void prep_kernel(const float* __restrict__ q,
                            const float* __restrict__ v,
                            const float* __restrict__ Wv,
                            const float* __restrict__ Wo,
                            const float* __restrict__ Wq,
                            const float* __restrict__ bq,
                            const float* __restrict__ Woff,
                            const float* __restrict__ boff,
                            const float* __restrict__ Wattn,
                            const float* __restrict__ battn) {
    const int QT = ROWS * Cc / 4;          // 2097152
    const int VT = Nn * Cc / 4;            // 262144
    const int WT = Cc * Cc;                // 65536
    const int FT = NF * Cc;                // 32768 (weight fold)
    int idx = blockIdx.x * blockDim.x + threadIdx.x;
    if (idx < QT) {
        float4 a = reinterpret_cast<const float4*>(q)[idx];
        __half2 h2[2];
        h2[0] = __floats2half2_rn(a.x, a.y);
        h2[1] = __floats2half2_rn(a.z, a.w);
        *(uint2*)&g_q16[(size_t)idx * 4] = *(const uint2*)h2;
    } else if (idx < QT + VT) {
        int li = idx - QT;
        const float4* v4 = reinterpret_cast<const float4*>(v);
        float4 a = v4[li], b = v4[li + VT], c = v4[li + 2 * VT], d = v4[li + 3 * VT];
        __half2 h2[2];
        h2[0] = __floats2half2_rn(0.25f * (a.x + b.x + c.x + d.x),
                                  0.25f * (a.y + b.y + c.y + d.y));
        h2[1] = __floats2half2_rn(0.25f * (a.z + b.z + c.z + d.z),
                                  0.25f * (a.w + b.w + c.w + d.w));
        *(uint2*)&g_vm16[li * 4] = *(const uint2*)h2;
    } else if (idx < QT + VT + WT) {
        int li = idx - QT - VT;
        int n = li / Cc, k = li % Cc;
        g_WvT[li] = __float2half_rn(Wv[k * Cc + n]);
    } else if (idx < QT + VT + 2 * WT) {
        int li = idx - QT - VT - WT;
        int n = li / Cc, k = li % Cc;
        g_WoT[li] = __float2half_rn(Wo[k * Cc + n]);
    } else if (idx < QT + VT + 2 * WT + FT) {
        int li = idx - QT - VT - 2 * WT;
        int k = li / NF, c = li % NF;
        float s = 0.f;
        if (c < 96) {
            const float* wq = Wq + k * Cc;
            if (c < 64) {
#pragma unroll 8
                for (int j = 0; j < Cc; j++) s = fmaf(wq[j], Woff[j * 64 + c], s);
            } else {
                int cc2 = c - 64;
#pragma unroll 8
                for (int j = 0; j < Cc; j++) s = fmaf(wq[j], Wattn[j * 32 + cc2], s);
            }
        }
        g_WfT[c * Cc + k] = __float2half_rn(s);
    } else if (idx < QT + VT + 2 * WT + FT + NF) {
        int j = idx - QT - VT - 2 * WT - FT;
        if (j < 64) {
            float s = boff[j];
            for (int k = 0; k < Cc; k++) s += bq[k] * Woff[k * 64 + j];
            g_bfold[j] = s;
        } else if (j < 96) {
            int jj = j - 64;
            float s = battn[jj];
            for (int k = 0; k < Cc; k++) s += bq[k] * Wattn[k * 32 + jj];
            g_bfold[j] = s;
        } else {
            g_bfold[j] = 0.f;
        }
    }
}

// ---------------------------------------------------------------------------
extern "C" void kernel_launch(void* const* d_in, const int* in_sizes, int n_in,
                              void* d_out, int out_size) {
    (void)in_sizes; (void)n_in; (void)out_size;
    const float* q     = (const float*)d_in[0];
    const float* v     = (const float*)d_in[2];
    const float* Wq    = (const float*)d_in[3];
    const float* bq    = (const float*)d_in[4];
    const float* Wv    = (const float*)d_in[7];
    const float* bv    = (const float*)d_in[8];
    const float* Wo    = (const float*)d_in[9];
    const float* bo    = (const float*)d_in[10];
    const float* Woff  = (const float*)d_in[11];
    const float* boff  = (const float*)d_in[12];
    const float* Wattn = (const float*)d_in[13];
    const float* battn = (const float*)d_in[14];
    float* out = (float*)d_out;

    float* p_bfold;
    __half *p_q16, *p_vm16, *p_vpmh, *p_WvT, *p_WoT, *p_WfT, *p_pre16;
    cudaGetSymbolAddress((void**)&p_q16,   g_q16);
    cudaGetSymbolAddress((void**)&p_vm16,  g_vm16);
    cudaGetSymbolAddress((void**)&p_vpmh,  g_vpm_h);
    cudaGetSymbolAddress((void**)&p_bfold, g_bfold);
    cudaGetSymbolAddress((void**)&p_pre16, g_pre16);
    cudaGetSymbolAddress((void**)&p_WvT,   g_WvT);
    cudaGetSymbolAddress((void**)&p_WoT,   g_WoT);
    cudaGetSymbolAddress((void**)&p_WfT,   g_WfT);

    // 1. fused prep (conversions, transposes, weight fold, bias fold)
    {
        int tot = ROWS * Cc / 4 + Nn * Cc / 4 + 2 * Cc * Cc + NF * Cc + NF;
        prep_kernel<<<(tot + 255) / 256, 256>>>(q, v, Wv, Wo, Wq, bq, Woff,
                                                boff, Wattn, battn);
    }

    // 2. vpm (fp16) = vmean @ Wv + bv   (BN=64, grid 128)
    gemm_f16<64, true><<<dim3(Cc / 64, Nn / 128), 256>>>(
        p_vm16, p_WvT, bv, p_vpmh, Nn, Cc);

    // 3. fused offattn GEMM + sampling -> pre16  (BM=64, 512 blocks)
    fused_offattn_sample<<<ROWS / 64, 256>>>(p_q16, p_WfT, p_bfold);

    // 4. out = pre @ Wo + bo   (BN=128, grid 512)
    gemm_f16<128, false><<<dim3(Cc / 128, ROWS / 128), 256>>>(
        p_pre16, p_WoT, bo, out, ROWS, Cc);
}

// round 13
// speedup vs baseline: 1.0332x; 1.0332x over previous
#include <cuda_runtime.h>
#include <cuda_bf16.h>
#include <cuda_fp16.h>
#include <cstdint>

// ---------------------------------------------------------------------------
// DeformableAttention (B=8, N=4096, C=256, S=4, NH=8, NL=1, NP=4, HD=32)
//
// fp16 mma.sync pipeline v4 (3 launches):
//   1. prep: q->fp16; vmean->fp16; Wv,Wo,Wfold transposes; bias fold
//   2. vpm   = vmean @ Wv + bv            (BN=64 GEMM, fp16 out)
//   3. mega (BM=32, 1024 blocks): offattn GEMM -> softmax + bilinear
//      sampling (pre tile kept in smem, ldmatrix layout) -> out GEMM -> out
// ---------------------------------------------------------------------------

namespace {
constexpr int Bn   = 8;
constexpr int Nn   = 4096;
constexpr int Cc   = 256;   // K for all GEMMs
constexpr int NHh  = 8;
constexpr int NPp  = 4;
constexpr int HDd  = 32;
constexpr int ROWS = Bn * Nn;    // 32768
constexpr int GW   = 64;
constexpr int NF   = 128;        // padded offattn width
}

// -------------------- scratch (static device globals) ----------------------
__device__ __align__(16) __half g_q16[(size_t)ROWS * Cc];
__device__ __align__(16) __half g_vm16[Nn * Cc];
__device__ __align__(16) __half g_vpm_h[Nn * Cc];
__device__ __align__(16) float g_bfold[NF];
__device__ __align__(16) __half g_WvT[Cc * Cc];
__device__ __align__(16) __half g_WoT[Cc * Cc];
__device__ __align__(16) __half g_WfT[NF * Cc];

// -------------------- helpers ----------------------------------------------
__device__ __forceinline__ void mma_f16(float c[4], const uint32_t a[4],
                                        const uint32_t b[2]) {
    asm volatile(
        "mma.sync.aligned.m16n8k16.row.col.f32.f16.f16.f32 "
        "{%0,%1,%2,%3}, {%4,%5,%6,%7}, {%8,%9}, {%0,%1,%2,%3};\n"
        : "+f"(c[0]), "+f"(c[1]), "+f"(c[2]), "+f"(c[3])
        : "r"(a[0]), "r"(a[1]), "r"(a[2]), "r"(a[3]), "r"(b[0]), "r"(b[1]));
}

__device__ __forceinline__ void ldmx4(uint32_t r[4], uint32_t addr) {
    asm volatile(
        "ldmatrix.sync.aligned.m8n8.x4.shared.b16 {%0,%1,%2,%3}, [%4];\n"
        : "=r"(r[0]), "=r"(r[1]), "=r"(r[2]), "=r"(r[3]) : "r"(addr));
}

__device__ __forceinline__ void cp_async16(uint32_t dst, const void* src) {
    asm volatile("cp.async.cg.shared.global [%0], [%1], 16;\n"
                 :: "r"(dst), "l"(src));
}
__device__ __forceinline__ void cp_commit() {
    asm volatile("cp.async.commit_group;\n");
}
template <int NN>
__device__ __forceinline__ void cp_wait() {
    asm volatile("cp.async.wait_group %0;\n" :: "n"(NN));
}

// -------------------- GEMM: C = A @ Bt^T + bias (fp16 operands) ------------
// BM=128, BN=64, BK=32, 3-stage cp.async, ldmatrix + XOR swizzle. (vpm only)
template <bool HALF_OUT>
__global__ void __launch_bounds__(256, 2)
gemm_f16(const __half* __restrict__ Ag,
         const __half* __restrict__ Bg,
         const float* __restrict__ bias, void* __restrict__ Cout,
         int M, int N) {
    constexpr int K = Cc, BM = 128, BN = 64, BK = 32;
    constexpr int NK = K / BK;     // 8
    constexpr int STB = 12288;
    __shared__ __align__(128) uint8_t smem[3 * STB];
    const uint32_t sb = (uint32_t)__cvta_generic_to_shared(smem);

    const int t = threadIdx.x, w = t >> 5, l = t & 31;
    const int wm = w & 3, wn = w >> 2;
    const int g = l >> 2, qq = l & 3;
    const int blockRow = blockIdx.y * BM;
    const int blockCol = blockIdx.x * BN;
    const int lr = t >> 2, lc = t & 3;

    float acc[2][4][4];
#pragma unroll
    for (int i = 0; i < 2; i++)
#pragma unroll
        for (int j = 0; j < 4; j++)
#pragma unroll
            for (int x = 0; x < 4; x++) acc[i][j][x] = 0.f;

    auto stage = [&](int buf, int k0) {
        const uint32_t base = sb + buf * STB;
#pragma unroll
        for (int j = 0; j < 2; j++) {
            int row = lr + j * 64;
            uint32_t sw = (uint32_t)row * 64 + (uint32_t)((lc ^ ((row >> 1) & 3)) * 16);
            cp_async16(base + sw, Ag + (size_t)(blockRow + row) * K + k0 + lc * 8);
        }
        {
            uint32_t sw = (uint32_t)lr * 64 + (uint32_t)((lc ^ ((lr >> 1) & 3)) * 16);
            cp_async16(base + 8192 + sw, Bg + (size_t)(blockCol + lr) * K + k0 + lc * 8);
        }
        cp_commit();
    };

    auto compute = [&](int buf) {
        const uint32_t base = sb + buf * STB;
        const int seg = l >> 3, sl = l & 7;
#pragma unroll
        for (int ks = 0; ks < 2; ks++) {
            uint32_t bF[4][2];
#pragma unroll
            for (int nt = 0; nt < 2; nt++) {
                int r = wn * 32 + nt * 16 + (seg >> 1) * 8 + sl;
                int c = ks * 2 + (seg & 1);
                uint32_t addr = (uint32_t)r * 64 + (uint32_t)((c ^ ((r >> 1) & 3)) * 16);
                uint32_t tmp[4];
                ldmx4(tmp, base + 8192 + addr);
                bF[nt * 2][0] = tmp[0]; bF[nt * 2][1] = tmp[1];
                bF[nt * 2 + 1][0] = tmp[2]; bF[nt * 2 + 1][1] = tmp[3];
            }
            uint32_t aF[2][4];
#pragma unroll
            for (int mt = 0; mt < 2; mt++) {
                int r = wm * 32 + mt * 16 + (seg & 1) * 8 + sl;
                int c = ks * 2 + (seg >> 1);
                uint32_t addr = (uint32_t)r * 64 + (uint32_t)((c ^ ((r >> 1) & 3)) * 16);
                ldmx4(aF[mt], base + addr);
            }
#pragma unroll
            for (int mt = 0; mt < 2; mt++)
#pragma unroll
                for (int nf = 0; nf < 4; nf++)
                    mma_f16(acc[mt][nf], aF[mt], bF[nf]);
        }
    };

    stage(0, 0);
    stage(1, BK);
    for (int kt = 0; kt < NK; kt++) {
        if (kt + 2 < NK) cp_wait<1>();
        else             cp_wait<0>();
        __syncthreads();
        if (kt + 2 < NK) stage((kt + 2) % 3, (kt + 2) * BK);
        compute(kt % 3);
    }

#pragma unroll
    for (int mt = 0; mt < 2; mt++) {
        int row = blockRow + wm * 32 + mt * 16 + g;
#pragma unroll
        for (int nf = 0; nf < 4; nf++) {
            int col = blockCol + wn * 32 + nf * 8 + 2 * qq;
            float2 bb = *(const float2*)&bias[col];
            float v00 = acc[mt][nf][0] + bb.x, v01 = acc[mt][nf][1] + bb.y;
            float v10 = acc[mt][nf][2] + bb.x, v11 = acc[mt][nf][3] + bb.y;
            if (HALF_OUT) {
                __half2* Ch = (__half2*)Cout;
                Ch[((size_t)row * N + col) >> 1]       = __floats2half2_rn(v00, v01);
                Ch[((size_t)(row + 8) * N + col) >> 1] = __floats2half2_rn(v10, v11);
            } else {
                float* Cf = (float*)Cout;
                *(float2*)&Cf[(size_t)row * N + col]       = make_float2(v00, v01);
                *(float2*)&Cf[(size_t)(row + 8) * N + col] = make_float2(v10, v11);
            }
        }
    }
}

// -------------------- mega: offattn GEMM + sampling + out GEMM -------------
// BM=32 rows/block, 1024 blocks, 256 threads.
// smem (48KB static), lifetime-disjoint regions:
//   PRE  [0,16K):   pre fp16, 8 k-chunks x [32 rows][32 cols] ldmatrix layout
//   SOA  [16K,28K): offattn fp32 [32][96]       (written at phase-A epilogue)
//   A-stages: 3 x 10KB at [16K,46.5K)           (phase A only)
//   C-stages: CS0 [32K,48K), CS1 [16K,32K)      (phase C only; CS1 covers SOA)
__global__ void __launch_bounds__(256, 2)
mega_kernel(const __half* __restrict__ Ag,     // q16
            const __half* __restrict__ Bf,     // WfT [128][256]
            const float* __restrict__ bfold,
            const __half* __restrict__ WoT,    // [256][256]
            const float* __restrict__ bo,
            float* __restrict__ out) {
    constexpr int K = Cc, BK = 32, NK = 8;
    constexpr uint32_t PRE = 0, SOA = 16384;
    constexpr uint32_t ASTG = 16384, ASTG_SZ = 10240;
    constexpr uint32_t CS0 = 32768, CS1 = 16384;
    __shared__ __align__(128) uint8_t smem[49152];
    const uint32_t sb = (uint32_t)__cvta_generic_to_shared(smem);
    float* s_oa = (float*)(smem + SOA);

    const int t = threadIdx.x, w = t >> 5, l = t & 31;
    const int wm = w & 1, wn = w >> 1;       // 2 x 4 warp grid
    const int g = l >> 2, qq = l & 3;
    const int seg = l >> 3, sl = l & 7;
    const int blockRow = blockIdx.x * 32;

    // ======== Phase A: offattn GEMM (32 x 128 = q_tile @ WfT^T) ========
    {
        float acc[4][4];
#pragma unroll
        for (int j = 0; j < 4; j++)
#pragma unroll
            for (int x = 0; x < 4; x++) acc[j][x] = 0.f;

        auto stageA = [&](int buf, int k0) {
            const uint32_t base = sb + ASTG + buf * ASTG_SZ;
            if (t < 128) {                       // A: 32 rows x 4 chunks
                int row = t >> 2, lc = t & 3;
                uint32_t sw = (uint32_t)row * 64 + (uint32_t)((lc ^ ((row >> 1) & 3)) * 16);
                cp_async16(base + sw, Ag + (size_t)(blockRow + row) * K + k0 + lc * 8);
            }
#pragma unroll
            for (int j = 0; j < 2; j++) {        // B: 128 rows x 4 chunks
                int ch = t + j * 256;
                int row = ch >> 2, lc = ch & 3;
                uint32_t sw = (uint32_t)row * 64 + (uint32_t)((lc ^ ((row >> 1) & 3)) * 16);
                cp_async16(base + 2048 + sw, Bf + (size_t)row * K + k0 + lc * 8);
            }
            cp_commit();
        };

        auto computeA = [&](int buf) {
            const uint32_t base = sb + ASTG + buf * ASTG_SZ;
#pragma unroll
            for (int ks = 0; ks < 2; ks++) {
                uint32_t bF[4][2];
#pragma unroll
                for (int nt = 0; nt < 2; nt++) {
                    int r = wn * 32 + nt * 16 + (seg >> 1) * 8 + sl;
                    int c = ks * 2 + (seg & 1);
                    uint32_t addr = (uint32_t)r * 64 + (uint32_t)((c ^ ((r >> 1) & 3)) * 16);
                    uint32_t tmp[4];
                    ldmx4(tmp, base + 2048 + addr);
                    bF[nt * 2][0] = tmp[0]; bF[nt * 2][1] = tmp[1];
                    bF[nt * 2 + 1][0] = tmp[2]; bF[nt * 2 + 1][1] = tmp[3];
                }
                uint32_t aF[4];
                int r = wm * 16 + (seg & 1) * 8 + sl;
                int c = ks * 2 + (seg >> 1);
                uint32_t addr = (uint32_t)r * 64 + (uint32_t)((c ^ ((r >> 1) & 3)) * 16);
                ldmx4(aF, base + addr);
#pragma unroll
                for (int nf = 0; nf < 4; nf++)
                    mma_f16(acc[nf], aF, bF[nf]);
            }
        };

        stageA(0, 0);
        stageA(1, BK);
        for (int kt = 0; kt < NK; kt++) {
            if (kt + 2 < NK) cp_wait<1>();
            else             cp_wait<0>();
            __syncthreads();
            if (kt + 2 < NK) stageA((kt + 2) % 3, (kt + 2) * BK);
            computeA(kt % 3);
        }
        __syncthreads();   // stages dead; SOA overlay safe

        int rl = wm * 16 + g;
#pragma unroll
        for (int nf = 0; nf < 4; nf++) {
            int col = wn * 32 + nf * 8 + 2 * qq;
            if (col < 96) {
                float b0 = bfold[col], b1 = bfold[col + 1];
                s_oa[rl * 96 + col]           = acc[nf][0] + b0;
                s_oa[rl * 96 + col + 1]       = acc[nf][1] + b1;
                s_oa[(rl + 8) * 96 + col]     = acc[nf][2] + b0;
                s_oa[(rl + 8) * 96 + col + 1] = acc[nf][3] + b1;
            }
        }
        __syncthreads();
    }

    // pre-issue out-GEMM stage 0 (CS0 disjoint from SOA/PRE) — overlaps sampling
    {
#pragma unroll
        for (int j = 0; j < 4; j++) {
            int ch = t + j * 256;                // 1024 chunks: [256 rows][32c]
            int row = ch >> 2, lc = ch & 3;
            uint32_t sw = (uint32_t)row * 64 + (uint32_t)((lc ^ ((row >> 1) & 3)) * 16);
            cp_async16(sb + CS0 + sw, WoT + (size_t)row * K + lc * 8);
        }
        cp_commit();
    }

    // ======== Phase B: softmax + bilinear sampling -> PRE (smem) ========
    for (int rl = w * 4; rl < w * 4 + 4; rl++) {
        const int row = blockRow + rl;
        const int n = row & (Nn - 1);
        const float refx = (float)(n & (GW - 1)) * (1.0f / 63.0f);
        const float refy = (float)(n >> 6) * (1.0f / 63.0f);
        const float* oa = s_oa + rl * 96;

#pragma unroll
        for (int h = 0; h < NHh; h++) {
            float l0 = oa[64 + h * 4 + 0];
            float l1 = oa[64 + h * 4 + 1];
            float l2 = oa[64 + h * 4 + 2];
            float l3 = oa[64 + h * 4 + 3];
            float m  = fmaxf(fmaxf(l0, l1), fmaxf(l2, l3));
            float e0 = __expf(l0 - m), e1 = __expf(l1 - m);
            float e2 = __expf(l2 - m), e3 = __expf(l3 - m);
            float inv = 1.0f / (e0 + e1 + e2 + e3);
            float wp[4] = {e0 * inv, e1 * inv, e2 * inv, e3 * inv};

            const __half* fmap = g_vpm_h + h * HDd + l;
            float acc2 = 0.f;
#pragma unroll
            for (int p = 0; p < NPp; p++) {
                float ox = oa[h * 8 + p * 2 + 0];
                float oy = oa[h * 8 + p * 2 + 1];
                float lx = fminf(fmaxf(refx + ox, 0.f), 1.f);
                float ly = fminf(fmaxf(refy + oy, 0.f), 1.f);
                float x = lx * (float)GW - 0.5f;
                float y = ly * (float)GW - 0.5f;
                float xf = floorf(x), yf = floorf(y);
                float tx = x - xf, ty = y - yf;
                int x0 = (int)xf, y0 = (int)yf;
                int x1 = x0 + 1, y1 = y0 + 1;
                bool vx0 = (x0 >= 0), vx1 = (x1 < GW);
                bool vy0 = (y0 >= 0), vy1 = (y1 < GW);
                float w00 = (1.f - tx) * (1.f - ty);
                float w01 = tx * (1.f - ty);
                float w10 = (1.f - tx) * ty;
                float w11 = tx * ty;
                float a = 0.f;
                if (vx0 && vy0) a = fmaf(w00, __half2float(fmap[(size_t)(y0 * GW + x0) * Cc]), a);
                if (vx1 && vy0) a = fmaf(w01, __half2float(fmap[(size_t)(y0 * GW + x1) * Cc]), a);
                if (vx0 && vy1) a = fmaf(w10, __half2float(fmap[(size_t)(y1 * GW + x0) * Cc]), a);
                if (vx1 && vy1) a = fmaf(w11, __half2float(fmap[(size_t)(y1 * GW + x1) * Cc]), a);
                acc2 = fmaf(wp[p], a, acc2);
            }
            // write into PRE (chunk h), ldmatrix-compatible swizzled layout
            uint32_t boff = PRE + (uint32_t)h * 2048 + (uint32_t)rl * 64 +
                            ((((uint32_t)l >> 3) ^ ((uint32_t)(rl >> 1) & 3)) << 4) +
                            ((uint32_t)(l & 7)) * 2;
            *(__half*)(smem + boff) = __float2half_rn(acc2);
        }
    }
    __syncthreads();   // PRE complete; SOA dead -> C stages may use CS1

    // ======== Phase C: out GEMM (32 x 256 = pre @ WoT^T) + bo ========
    {
        float acc[8][4];
#pragma unroll
        for (int j = 0; j < 8; j++)
#pragma unroll
            for (int x = 0; x < 4; x++) acc[j][x] = 0.f;

        auto stageC = [&](int buf, int k0) {
            const uint32_t base = sb + (buf ? CS1 : CS0);
#pragma unroll
            for (int j = 0; j < 4; j++) {
                int ch = t + j * 256;
                int row = ch >> 2, lc = ch & 3;
                uint32_t sw = (uint32_t)row * 64 + (uint32_t)((lc ^ ((row >> 1) & 3)) * 16);
                cp_async16(base + sw, WoT + (size_t)row * K + k0 + lc * 8);
            }
            cp_commit();
        };

        for (int kt = 0; kt < NK; kt++) {
            cp_wait<0>();
            __syncthreads();
            if (kt + 1 < NK) stageC((kt + 1) & 1, (kt + 1) * BK);
            const uint32_t base = sb + ((kt & 1) ? CS1 : CS0);
#pragma unroll
            for (int ks = 0; ks < 2; ks++) {
                uint32_t bF[8][2];
#pragma unroll
                for (int nt = 0; nt < 4; nt++) {
                    int r = wn * 64 + nt * 16 + (seg >> 1) * 8 + sl;
                    int c = ks * 2 + (seg & 1);
                    uint32_t addr = (uint32_t)r * 64 + (uint32_t)((c ^ ((r >> 1) & 3)) * 16);
                    uint32_t tmp[4];
                    ldmx4(tmp, base + addr);
                    bF[nt * 2][0] = tmp[0]; bF[nt * 2][1] = tmp[1];
                    bF[nt * 2 + 1][0] = tmp[2]; bF[nt * 2 + 1][1] = tmp[3];
                }
                uint32_t aF[4];
                int r = wm * 16 + (seg & 1) * 8 + sl;
                int c = ks * 2 + (seg >> 1);
                uint32_t addr = PRE + (uint32_t)kt * 2048 + (uint32_t)r * 64 +
                                (uint32_t)((c ^ ((r >> 1) & 3)) * 16);
                ldmx4(aF, sb + addr);
#pragma unroll
                for (int nf = 0; nf < 8; nf++)
                    mma_f16(acc[nf], aF, bF[nf]);
            }
        }

        int row = blockRow + wm * 16 + g;
#pragma unroll
        for (int nf = 0; nf < 8; nf++) {
            int col = wn * 64 + nf * 8 + 2 * qq;
            float2 bb = *(const float2*)&bo[col];
            *(float2*)&out[(size_t)row * Cc + col] =
                make_float2(acc[nf][0] + bb.x, acc[nf][1] + bb.y);
            *(float2*)&out[(size_t)(row + 8) * Cc + col] =
                make_float2(acc[nf][2] + bb.x, acc[nf][3] + bb.y);
        }
    }
}

// -------------------- prep: conversions + transposes + fold + bias ---------
__global__ void prep_kernel(const float* __restrict__ q,
                            const float* __restrict__ v,
                            const float* __restrict__ Wv,
                            const float* __restrict__ Wo,
                            const float* __restrict__ Wq,
                            const float* __restrict__ bq,
                            const float* __restrict__ Woff,
                            const float* __restrict__ boff,
                            const float* __restrict__ Wattn,
                            const float* __restrict__ battn) {
    const int QT = ROWS * Cc / 4;
    const int VT = Nn * Cc / 4;
    const int WT = Cc * Cc;
    const int FT = NF * Cc;
    int idx = blockIdx.x * blockDim.x + threadIdx.x;
    if (idx < QT) {
        float4 a = reinterpret_cast<const float4*>(q)[idx];
        __half2 h2[2];
        h2[0] = __floats2half2_rn(a.x, a.y);
        h2[1] = __floats2half2_rn(a.z, a.w);
        *(uint2*)&g_q16[(size_t)idx * 4] = *(const uint2*)h2;
    } else if (idx < QT + VT) {
        int li = idx - QT;
        const float4* v4 = reinterpret_cast<const float4*>(v);
        float4 a = v4[li], b = v4[li + VT], c = v4[li + 2 * VT], d = v4[li + 3 * VT];
        __half2 h2[2];
        h2[0] = __floats2half2_rn(0.25f * (a.x + b.x + c.x + d.x),
                                  0.25f * (a.y + b.y + c.y + d.y));
        h2[1] = __floats2half2_rn(0.25f * (a.z + b.z + c.z + d.z),
                                  0.25f * (a.w + b.w + c.w + d.w));
        *(uint2*)&g_vm16[li * 4] = *(const uint2*)h2;
    } else if (idx < QT + VT + WT) {
        int li = idx - QT - VT;
        int n = li / Cc, k = li % Cc;
        g_WvT[li] = __float2half_rn(Wv[k * Cc + n]);
    } else if (idx < QT + VT + 2 * WT) {
        int li = idx - QT - VT - WT;
        int n = li / Cc, k = li % Cc;
        g_WoT[li] = __float2half_rn(Wo[k * Cc + n]);
    } else if (idx < QT + VT + 2 * WT + FT) {
        int li = idx - QT - VT - 2 * WT;
        int k = li / NF, c = li % NF;
        float s = 0.f;
        if (c < 96) {
            const float* wq = Wq + k * Cc;
            if (c < 64) {
#pragma unroll 8
                for (int j = 0; j < Cc; j++) s = fmaf(wq[j], Woff[j * 64 + c], s);
            } else {
                int cc2 = c - 64;
#pragma unroll 8
                for (int j = 0; j < Cc; j++) s = fmaf(wq[j], Wattn[j * 32 + cc2], s);
            }
        }
        g_WfT[c * Cc + k] = __float2half_rn(s);
    } else if (idx < QT + VT + 2 * WT + FT + NF) {
        int j = idx - QT - VT - 2 * WT - FT;
        if (j < 64) {
            float s = boff[j];
            for (int k = 0; k < Cc; k++) s += bq[k] * Woff[k * 64 + j];
            g_bfold[j] = s;
        } else if (j < 96) {
            int jj = j - 64;
            float s = battn[jj];
            for (int k = 0; k < Cc; k++) s += bq[k] * Wattn[k * 32 + jj];
            g_bfold[j] = s;
        } else {
            g_bfold[j] = 0.f;
        }
    }
}

// ---------------------------------------------------------------------------
extern "C" void kernel_launch(void* const* d_in, const int* in_sizes, int n_in,
                              void* d_out, int out_size) {
    (void)in_sizes; (void)n_in; (void)out_size;
    const float* q     = (const float*)d_in[0];
    const float* v     = (const float*)d_in[2];
    const float* Wq    = (const float*)d_in[3];
    const float* bq    = (const float*)d_in[4];
    const float* Wv    = (const float*)d_in[7];
    const float* bv    = (const float*)d_in[8];
    const float* Wo    = (const float*)d_in[9];
    const float* bo    = (const float*)d_in[10];
    const float* Woff  = (const float*)d_in[11];
    const float* boff  = (const float*)d_in[12];
    const float* Wattn = (const float*)d_in[13];
    const float* battn = (const float*)d_in[14];
    float* out = (float*)d_out;

    float* p_bfold;
    __half *p_q16, *p_vm16, *p_vpmh, *p_WvT, *p_WoT, *p_WfT;
    cudaGetSymbolAddress((void**)&p_q16,   g_q16);
    cudaGetSymbolAddress((void**)&p_vm16,  g_vm16);
    cudaGetSymbolAddress((void**)&p_vpmh,  g_vpm_h);
    cudaGetSymbolAddress((void**)&p_bfold, g_bfold);
    cudaGetSymbolAddress((void**)&p_WvT,   g_WvT);
    cudaGetSymbolAddress((void**)&p_WoT,   g_WoT);
    cudaGetSymbolAddress((void**)&p_WfT,   g_WfT);

    // 1. fused prep
    {
        int tot = ROWS * Cc / 4 + Nn * Cc / 4 + 2 * Cc * Cc + NF * Cc + NF;
        prep_kernel<<<(tot + 255) / 256, 256>>>(q, v, Wv, Wo, Wq, bq, Woff,
                                                boff, Wattn, battn);
    }

    // 2. vpm (fp16) = vmean @ Wv + bv
    gemm_f16<true><<<dim3(Cc / 64, Nn / 128), 256>>>(
        p_vm16, p_WvT, bv, p_vpmh, Nn, Cc);

    // 3. mega: offattn GEMM + sampling + out GEMM
    mega_kernel<<<ROWS / 32, 256>>>(p_q16, p_WfT, p_bfold, p_WoT, bo, out);
}

// round 14
// speedup vs baseline: 1.1276x; 1.0913x over previous
#include <cuda_runtime.h>
#include <cuda_bf16.h>
#include <cuda_fp16.h>
#include <cstdint>

// ---------------------------------------------------------------------------
// DeformableAttention (B=8, N=4096, C=256, S=4, NH=8, NL=1, NP=4, HD=32)
//
// fp16 mma.sync pipeline v5 (3 launches):
//   1. prep: vmean->fp16; Wv,Wo transposes; weight fold; bias fold
//            (q conversion moved into mega — no q16 global round trip)
//   2. vpm   = vmean @ Wv + bv            (BN=64 GEMM, fp16 out)
//   3. mega (BM=32, 1024 blocks): q fp32 -> smem fp16 (PRE region) ->
//      offattn GEMM -> softmax + bilinear sampling (pre into PRE) ->
//      out GEMM -> out
// ---------------------------------------------------------------------------

namespace {
constexpr int Bn   = 8;
constexpr int Nn   = 4096;
constexpr int Cc   = 256;   // K for all GEMMs
constexpr int NHh  = 8;
constexpr int NPp  = 4;
constexpr int HDd  = 32;
constexpr int ROWS = Bn * Nn;    // 32768
constexpr int GW   = 64;
constexpr int NF   = 128;        // padded offattn width
}

// -------------------- scratch (static device globals) ----------------------
__device__ __align__(16) __half g_vm16[Nn * Cc];
__device__ __align__(16) __half g_vpm_h[Nn * Cc];
__device__ __align__(16) float g_bfold[NF];
__device__ __align__(16) __half g_WvT[Cc * Cc];
__device__ __align__(16) __half g_WoT[Cc * Cc];
__device__ __align__(16) __half g_WfT[NF * Cc];

// -------------------- helpers ----------------------------------------------
__device__ __forceinline__ void mma_f16(float c[4], const uint32_t a[4],
                                        const uint32_t b[2]) {
    asm volatile(
        "mma.sync.aligned.m16n8k16.row.col.f32.f16.f16.f32 "
        "{%0,%1,%2,%3}, {%4,%5,%6,%7}, {%8,%9}, {%0,%1,%2,%3};\n"
        : "+f"(c[0]), "+f"(c[1]), "+f"(c[2]), "+f"(c[3])
        : "r"(a[0]), "r"(a[1]), "r"(a[2]), "r"(a[3]), "r"(b[0]), "r"(b[1]));
}

__device__ __forceinline__ void ldmx4(uint32_t r[4], uint32_t addr) {
    asm volatile(
        "ldmatrix.sync.aligned.m8n8.x4.shared.b16 {%0,%1,%2,%3}, [%4];\n"
        : "=r"(r[0]), "=r"(r[1]), "=r"(r[2]), "=r"(r[3]) : "r"(addr));
}

__device__ __forceinline__ void cp_async16(uint32_t dst, const void* src) {
    asm volatile("cp.async.cg.shared.global [%0], [%1], 16;\n"
                 :: "r"(dst), "l"(src));
}
__device__ __forceinline__ void cp_commit() {
    asm volatile("cp.async.commit_group;\n");
}
template <int NN>
__device__ __forceinline__ void cp_wait() {
    asm volatile("cp.async.wait_group %0;\n" :: "n"(NN));
}

// -------------------- GEMM: C = A @ Bt^T + bias (vpm only) -----------------
// BM=128, BN=64, BK=32, 3-stage cp.async, ldmatrix + XOR swizzle.
template <bool HALF_OUT>
__global__ void __launch_bounds__(256, 2)
gemm_f16(const __half* __restrict__ Ag,
         const __half* __restrict__ Bg,
         const float* __restrict__ bias, void* __restrict__ Cout,
         int M, int N) {
    constexpr int K = Cc, BM = 128, BN = 64, BK = 32;
    constexpr int NK = K / BK;     // 8
    constexpr int STB = 12288;
    __shared__ __align__(128) uint8_t smem[3 * STB];
    const uint32_t sb = (uint32_t)__cvta_generic_to_shared(smem);

    const int t = threadIdx.x, w = t >> 5, l = t & 31;
    const int wm = w & 3, wn = w >> 2;
    const int g = l >> 2, qq = l & 3;
    const int blockRow = blockIdx.y * BM;
    const int blockCol = blockIdx.x * BN;
    const int lr = t >> 2, lc = t & 3;

    float acc[2][4][4];
#pragma unroll
    for (int i = 0; i < 2; i++)
#pragma unroll
        for (int j = 0; j < 4; j++)
#pragma unroll
            for (int x = 0; x < 4; x++) acc[i][j][x] = 0.f;

    auto stage = [&](int buf, int k0) {
        const uint32_t base = sb + buf * STB;
#pragma unroll
        for (int j = 0; j < 2; j++) {
            int row = lr + j * 64;
            uint32_t sw = (uint32_t)row * 64 + (uint32_t)((lc ^ ((row >> 1) & 3)) * 16);
            cp_async16(base + sw, Ag + (size_t)(blockRow + row) * K + k0 + lc * 8);
        }
        {
            uint32_t sw = (uint32_t)lr * 64 + (uint32_t)((lc ^ ((lr >> 1) & 3)) * 16);
            cp_async16(base + 8192 + sw, Bg + (size_t)(blockCol + lr) * K + k0 + lc * 8);
        }
        cp_commit();
    };

    auto compute = [&](int buf) {
        const uint32_t base = sb + buf * STB;
        const int seg = l >> 3, sl = l & 7;
#pragma unroll
        for (int ks = 0; ks < 2; ks++) {
            uint32_t bF[4][2];
#pragma unroll
            for (int nt = 0; nt < 2; nt++) {
                int r = wn * 32 + nt * 16 + (seg >> 1) * 8 + sl;
                int c = ks * 2 + (seg & 1);
                uint32_t addr = (uint32_t)r * 64 + (uint32_t)((c ^ ((r >> 1) & 3)) * 16);
                uint32_t tmp[4];
                ldmx4(tmp, base + 8192 + addr);
                bF[nt * 2][0] = tmp[0]; bF[nt * 2][1] = tmp[1];
                bF[nt * 2 + 1][0] = tmp[2]; bF[nt * 2 + 1][1] = tmp[3];
            }
            uint32_t aF[2][4];
#pragma unroll
            for (int mt = 0; mt < 2; mt++) {
                int r = wm * 32 + mt * 16 + (seg & 1) * 8 + sl;
                int c = ks * 2 + (seg >> 1);
                uint32_t addr = (uint32_t)r * 64 + (uint32_t)((c ^ ((r >> 1) & 3)) * 16);
                ldmx4(aF[mt], base + addr);
            }
#pragma unroll
            for (int mt = 0; mt < 2; mt++)
#pragma unroll
                for (int nf = 0; nf < 4; nf++)
                    mma_f16(acc[mt][nf], aF[mt], bF[nf]);
        }
    };

    stage(0, 0);
    stage(1, BK);
    for (int kt = 0; kt < NK; kt++) {
        if (kt + 2 < NK) cp_wait<1>();
        else             cp_wait<0>();
        __syncthreads();
        if (kt + 2 < NK) stage((kt + 2) % 3, (kt + 2) * BK);
        compute(kt % 3);
    }

#pragma unroll
    for (int mt = 0; mt < 2; mt++) {
        int row = blockRow + wm * 32 + mt * 16 + g;
#pragma unroll
        for (int nf = 0; nf < 4; nf++) {
            int col = blockCol + wn * 32 + nf * 8 + 2 * qq;
            float2 bb = *(const float2*)&bias[col];
            float v00 = acc[mt][nf][0] + bb.x, v01 = acc[mt][nf][1] + bb.y;
            float v10 = acc[mt][nf][2] + bb.x, v11 = acc[mt][nf][3] + bb.y;
            if (HALF_OUT) {
                __half2* Ch = (__half2*)Cout;
                Ch[((size_t)row * N + col) >> 1]       = __floats2half2_rn(v00, v01);
                Ch[((size_t)(row + 8) * N + col) >> 1] = __floats2half2_rn(v10, v11);
            } else {
                float* Cf = (float*)Cout;
                *(float2*)&Cf[(size_t)row * N + col]       = make_float2(v00, v01);
                *(float2*)&Cf[(size_t)(row + 8) * N + col] = make_float2(v10, v11);
            }
        }
    }
}

// -------------------- mega: q convert + offattn GEMM + sampling + out GEMM -
// BM=32 rows/block, 1024 blocks, 256 threads.
// smem (48KB static), lifetime-disjoint regions:
//   PRE  [0,16K):   phase A: q fp16 (8 chunks x [32][32] ldmatrix layout);
//                   phase B/C: pre fp16 (same layout)
//   SOA  [16K,28K): offattn fp32 [32][96]  (phase A epilogue -> phase B)
//   A-stages (B operand only): 3 x 8KB at [16K,40K)   (phase A loop only)
//   C-stages: CS0 [32K,48K), CS1 [16K,32K)            (phase C only)
__global__ void __launch_bounds__(256, 2)
mega_kernel(const float* __restrict__ qg,      // q fp32
            const __half* __restrict__ Bf,     // WfT [128][256]
            const float* __restrict__ bfold,
            const __half* __restrict__ WoT,    // [256][256]
            const float* __restrict__ bo,
            float* __restrict__ out) {
    constexpr int K = Cc, BK = 32, NK = 8;
    constexpr uint32_t PRE = 0, SOA = 16384;
    constexpr uint32_t ASTG = 16384, ASTG_SZ = 8192;
    constexpr uint32_t CS0 = 32768, CS1 = 16384;
    __shared__ __align__(128) uint8_t smem[49152];
    const uint32_t sb = (uint32_t)__cvta_generic_to_shared(smem);
    float* s_oa = (float*)(smem + SOA);

    const int t = threadIdx.x, w = t >> 5, l = t & 31;
    const int wm = w & 1, wn = w >> 1;       // 2 x 4 warp grid
    const int g = l >> 2, qq = l & 3;
    const int seg = l >> 3, sl = l & 7;
    const int blockRow = blockIdx.x * 32;

    // ---- q preload: 32 x 256 fp32 -> fp16 into PRE (swizzled chunks) ----
    {
        const int row = t >> 3;              // 0..31
        const int g0 = t & 7;                // base 8-col group
#pragma unroll
        for (int j = 0; j < 4; j++) {
            int grp = g0 + j * 8;            // 0..31
            int col = grp * 8;
            const float* src = qg + (size_t)(blockRow + row) * K + col;
            float4 a = *(const float4*)src;
            float4 b = *(const float4*)(src + 4);
            __half2 h2[4];
            h2[0] = __floats2half2_rn(a.x, a.y);
            h2[1] = __floats2half2_rn(a.z, a.w);
            h2[2] = __floats2half2_rn(b.x, b.y);
            h2[3] = __floats2half2_rn(b.z, b.w);
            int kt = col >> 5;               // chunk
            int c16 = (col & 31) >> 3;       // 16B group within chunk
            uint32_t addr = PRE + (uint32_t)kt * 2048 + (uint32_t)row * 64 +
                            (uint32_t)((c16 ^ ((row >> 1) & 3)) << 4);
            *(uint4*)(smem + addr) = *(const uint4*)h2;
        }
    }

    // ======== Phase A: offattn GEMM (32 x 128 = q_tile @ WfT^T) ========
    {
        float acc[4][4];
#pragma unroll
        for (int j = 0; j < 4; j++)
#pragma unroll
            for (int x = 0; x < 4; x++) acc[j][x] = 0.f;

        auto stageA = [&](int buf, int k0) {
            const uint32_t base = sb + ASTG + buf * ASTG_SZ;
#pragma unroll
            for (int j = 0; j < 2; j++) {        // B: 128 rows x 4 chunks
                int ch = t + j * 256;
                int row = ch >> 2, lc = ch & 3;
                uint32_t sw = (uint32_t)row * 64 + (uint32_t)((lc ^ ((row >> 1) & 3)) * 16);
                cp_async16(base + sw, Bf + (size_t)row * K + k0 + lc * 8);
            }
            cp_commit();
        };

        auto computeA = [&](int buf, int kt) {
            const uint32_t base = sb + ASTG + buf * ASTG_SZ;
#pragma unroll
            for (int ks = 0; ks < 2; ks++) {
                uint32_t bF[4][2];
#pragma unroll
                for (int nt = 0; nt < 2; nt++) {
                    int r = wn * 32 + nt * 16 + (seg >> 1) * 8 + sl;
                    int c = ks * 2 + (seg & 1);
                    uint32_t addr = (uint32_t)r * 64 + (uint32_t)((c ^ ((r >> 1) & 3)) * 16);
                    uint32_t tmp[4];
                    ldmx4(tmp, base + addr);
                    bF[nt * 2][0] = tmp[0]; bF[nt * 2][1] = tmp[1];
                    bF[nt * 2 + 1][0] = tmp[2]; bF[nt * 2 + 1][1] = tmp[3];
                }
                uint32_t aF[4];
                int r = wm * 16 + (seg & 1) * 8 + sl;
                int c = ks * 2 + (seg >> 1);
                uint32_t addr = PRE + (uint32_t)kt * 2048 + (uint32_t)r * 64 +
                                (uint32_t)((c ^ ((r >> 1) & 3)) * 16);
                ldmx4(aF, sb + addr);
#pragma unroll
                for (int nf = 0; nf < 4; nf++)
                    mma_f16(acc[nf], aF, bF[nf]);
            }
        };

        stageA(0, 0);
        stageA(1, BK);
        for (int kt = 0; kt < NK; kt++) {
            if (kt + 2 < NK) cp_wait<1>();
            else             cp_wait<0>();
            __syncthreads();   // also orders q-preload STS before first reads
            if (kt + 2 < NK) stageA((kt + 2) % 3, (kt + 2) * BK);
            computeA(kt % 3, kt);
        }
        __syncthreads();   // stages dead; SOA overlay safe

        int rl = wm * 16 + g;
#pragma unroll
        for (int nf = 0; nf < 4; nf++) {
            int col = wn * 32 + nf * 8 + 2 * qq;
            if (col < 96) {
                float b0 = bfold[col], b1 = bfold[col + 1];
                s_oa[rl * 96 + col]           = acc[nf][0] + b0;
                s_oa[rl * 96 + col + 1]       = acc[nf][1] + b1;
                s_oa[(rl + 8) * 96 + col]     = acc[nf][2] + b0;
                s_oa[(rl + 8) * 96 + col + 1] = acc[nf][3] + b1;
            }
        }
        __syncthreads();
    }

    // pre-issue out-GEMM stage 0 (CS0 disjoint from SOA/PRE) — overlaps sampling
    {
#pragma unroll
        for (int j = 0; j < 4; j++) {
            int ch = t + j * 256;                // 1024 chunks: [256 rows][32c]
            int row = ch >> 2, lc = ch & 3;
            uint32_t sw = (uint32_t)row * 64 + (uint32_t)((lc ^ ((row >> 1) & 3)) * 16);
            cp_async16(sb + CS0 + sw, WoT + (size_t)row * K + lc * 8);
        }
        cp_commit();
    }

    // ======== Phase B: softmax + bilinear sampling -> PRE (smem) ========
    for (int rl = w * 4; rl < w * 4 + 4; rl++) {
        const int row = blockRow + rl;
        const int n = row & (Nn - 1);
        const float refx = (float)(n & (GW - 1)) * (1.0f / 63.0f);
        const float refy = (float)(n >> 6) * (1.0f / 63.0f);
        const float* oa = s_oa + rl * 96;

#pragma unroll
        for (int h = 0; h < NHh; h++) {
            float l0 = oa[64 + h * 4 + 0];
            float l1 = oa[64 + h * 4 + 1];
            float l2 = oa[64 + h * 4 + 2];
            float l3 = oa[64 + h * 4 + 3];
            float m  = fmaxf(fmaxf(l0, l1), fmaxf(l2, l3));
            float e0 = __expf(l0 - m), e1 = __expf(l1 - m);
            float e2 = __expf(l2 - m), e3 = __expf(l3 - m);
            float inv = 1.0f / (e0 + e1 + e2 + e3);
            float wp[4] = {e0 * inv, e1 * inv, e2 * inv, e3 * inv};

            const __half* fmap = g_vpm_h + h * HDd + l;
            float acc2 = 0.f;
#pragma unroll
            for (int p = 0; p < NPp; p++) {
                float ox = oa[h * 8 + p * 2 + 0];
                float oy = oa[h * 8 + p * 2 + 1];
                float lx = fminf(fmaxf(refx + ox, 0.f), 1.f);
                float ly = fminf(fmaxf(refy + oy, 0.f), 1.f);
                float x = lx * (float)GW - 0.5f;
                float y = ly * (float)GW - 0.5f;
                float xf = floorf(x), yf = floorf(y);
                float tx = x - xf, ty = y - yf;
                int x0 = (int)xf, y0 = (int)yf;
                int x1 = x0 + 1, y1 = y0 + 1;
                bool vx0 = (x0 >= 0), vx1 = (x1 < GW);
                bool vy0 = (y0 >= 0), vy1 = (y1 < GW);
                float w00 = (1.f - tx) * (1.f - ty);
                float w01 = tx * (1.f - ty);
                float w10 = (1.f - tx) * ty;
                float w11 = tx * ty;
                float a = 0.f;
                if (vx0 && vy0) a = fmaf(w00, __half2float(fmap[(size_t)(y0 * GW + x0) * Cc]), a);
                if (vx1 && vy0) a = fmaf(w01, __half2float(fmap[(size_t)(y0 * GW + x1) * Cc]), a);
                if (vx0 && vy1) a = fmaf(w10, __half2float(fmap[(size_t)(y1 * GW + x0) * Cc]), a);
                if (vx1 && vy1) a = fmaf(w11, __half2float(fmap[(size_t)(y1 * GW + x1) * Cc]), a);
                acc2 = fmaf(wp[p], a, acc2);
            }
            uint32_t boff = PRE + (uint32_t)h * 2048 + (uint32_t)rl * 64 +
                            ((((uint32_t)l >> 3) ^ ((uint32_t)(rl >> 1) & 3)) << 4) +
                            ((uint32_t)(l & 7)) * 2;
            *(__half*)(smem + boff) = __float2half_rn(acc2);
        }
    }
    __syncthreads();   // PRE complete; SOA dead -> C stages may use CS1

    // ======== Phase C: out GEMM (32 x 256 = pre @ WoT^T) + bo ========
    {
        float acc[8][4];
#pragma unroll
        for (int j = 0; j < 8; j++)
#pragma unroll
            for (int x = 0; x < 4; x++) acc[j][x] = 0.f;

        auto stageC = [&](int buf, int k0) {
            const uint32_t base = sb + (buf ? CS1 : CS0);
#pragma unroll
            for (int j = 0; j < 4; j++) {
                int ch = t + j * 256;
                int row = ch >> 2, lc = ch & 3;
                uint32_t sw = (uint32_t)row * 64 + (uint32_t)((lc ^ ((row >> 1) & 3)) * 16);
                cp_async16(base + sw, WoT + (size_t)row * K + k0 + lc * 8);
            }
            cp_commit();
        };

        for (int kt = 0; kt < NK; kt++) {
            cp_wait<0>();
            __syncthreads();
            if (kt + 1 < NK) stageC((kt + 1) & 1, (kt + 1) * BK);
            const uint32_t base = sb + ((kt & 1) ? CS1 : CS0);
#pragma unroll
            for (int ks = 0; ks < 2; ks++) {
                uint32_t bF[8][2];
#pragma unroll
                for (int nt = 0; nt < 4; nt++) {
                    int r = wn * 64 + nt * 16 + (seg >> 1) * 8 + sl;
                    int c = ks * 2 + (seg & 1);
                    uint32_t addr = (uint32_t)r * 64 + (uint32_t)((c ^ ((r >> 1) & 3)) * 16);
                    uint32_t tmp[4];
                    ldmx4(tmp, base + addr);
                    bF[nt * 2][0] = tmp[0]; bF[nt * 2][1] = tmp[1];
                    bF[nt * 2 + 1][0] = tmp[2]; bF[nt * 2 + 1][1] = tmp[3];
                }
                uint32_t aF[4];
                int r = wm * 16 + (seg & 1) * 8 + sl;
                int c = ks * 2 + (seg >> 1);
                uint32_t addr = PRE + (uint32_t)kt * 2048 + (uint32_t)r * 64 +
                                (uint32_t)((c ^ ((r >> 1) & 3)) * 16);
                ldmx4(aF, sb + addr);
#pragma unroll
                for (int nf = 0; nf < 8; nf++)
                    mma_f16(acc[nf], aF, bF[nf]);
            }
        }

        int row = blockRow + wm * 16 + g;
#pragma unroll
        for (int nf = 0; nf < 8; nf++) {
            int col = wn * 64 + nf * 8 + 2 * qq;
            float2 bb = *(const float2*)&bo[col];
            *(float2*)&out[(size_t)row * Cc + col] =
                make_float2(acc[nf][0] + bb.x, acc[nf][1] + bb.y);
            *(float2*)&out[(size_t)(row + 8) * Cc + col] =
                make_float2(acc[nf][2] + bb.x, acc[nf][3] + bb.y);
        }
    }
}

// -------------------- prep: vmean, transposes, fold, bias ------------------
__global__ void prep_kernel(const float* __restrict__ v,
                            const float* __restrict__ Wv,
                            const float* __restrict__ Wo,
                            const float* __restrict__ Wq,
                            const float* __restrict__ bq,
                            const float* __restrict__ Woff,
                            const float* __restrict__ boff,
                            const float* __restrict__ Wattn,
                            const float* __restrict__ battn) {
    const int VT = Nn * Cc / 4;            // 262144
    const int WT = Cc * Cc;                // 65536
    const int FT = NF * Cc;                // 32768 (weight fold)
    int idx = blockIdx.x * blockDim.x + threadIdx.x;
    if (idx < VT) {
        const float4* v4 = reinterpret_cast<const float4*>(v);
        float4 a = v4[idx], b = v4[idx + VT], c = v4[idx + 2 * VT], d = v4[idx + 3 * VT];
        __half2 h2[2];
        h2[0] = __floats2half2_rn(0.25f * (a.x + b.x + c.x + d.x),
                                  0.25f * (a.y + b.y + c.y + d.y));
        h2[1] = __floats2half2_rn(0.25f * (a.z + b.z + c.z + d.z),
                                  0.25f * (a.w + b.w + c.w + d.w));
        *(uint2*)&g_vm16[idx * 4] = *(const uint2*)h2;
    } else if (idx < VT + WT) {
        int li = idx - VT;
        int n = li / Cc, k = li % Cc;
        g_WvT[li] = __float2half_rn(Wv[k * Cc + n]);
    } else if (idx < VT + 2 * WT) {
        int li = idx - VT - WT;
        int n = li / Cc, k = li % Cc;
        g_WoT[li] = __float2half_rn(Wo[k * Cc + n]);
    } else if (idx < VT + 2 * WT + FT) {
        int li = idx - VT - 2 * WT;
        int k = li / NF, c = li % NF;
        float s = 0.f;
        if (c < 96) {
            const float* wq = Wq + k * Cc;
            if (c < 64) {
#pragma unroll 8
                for (int j = 0; j < Cc; j++) s = fmaf(wq[j], Woff[j * 64 + c], s);
            } else {
                int cc2 = c - 64;
#pragma unroll 8
                for (int j = 0; j < Cc; j++) s = fmaf(wq[j], Wattn[j * 32 + cc2], s);
            }
        }
        g_WfT[c * Cc + k] = __float2half_rn(s);
    } else if (idx < VT + 2 * WT + FT + NF) {
        int j = idx - VT - 2 * WT - FT;
        if (j < 64) {
            float s = boff[j];
            for (int k = 0; k < Cc; k++) s += bq[k] * Woff[k * 64 + j];
            g_bfold[j] = s;
        } else if (j < 96) {
            int jj = j - 64;
            float s = battn[jj];
            for (int k = 0; k < Cc; k++) s += bq[k] * Wattn[k * 32 + jj];
            g_bfold[j] = s;
        } else {
            g_bfold[j] = 0.f;
        }
    }
}

// ---------------------------------------------------------------------------
extern "C" void kernel_launch(void* const* d_in, const int* in_sizes, int n_in,
                              void* d_out, int out_size) {
    (void)in_sizes; (void)n_in; (void)out_size;
    const float* q     = (const float*)d_in[0];
    const float* v     = (const float*)d_in[2];
    const float* Wq    = (const float*)d_in[3];
    const float* bq    = (const float*)d_in[4];
    const float* Wv    = (const float*)d_in[7];
    const float* bv    = (const float*)d_in[8];
    const float* Wo    = (const float*)d_in[9];
    const float* bo    = (const float*)d_in[10];
    const float* Woff  = (const float*)d_in[11];
    const float* boff  = (const float*)d_in[12];
    const float* Wattn = (const float*)d_in[13];
    const float* battn = (const float*)d_in[14];
    float* out = (float*)d_out;

    float* p_bfold;
    __half *p_vm16, *p_vpmh, *p_WvT, *p_WoT, *p_WfT;
    cudaGetSymbolAddress((void**)&p_vm16,  g_vm16);
    cudaGetSymbolAddress((void**)&p_vpmh,  g_vpm_h);
    cudaGetSymbolAddress((void**)&p_bfold, g_bfold);
    cudaGetSymbolAddress((void**)&p_WvT,   g_WvT);
    cudaGetSymbolAddress((void**)&p_WoT,   g_WoT);
    cudaGetSymbolAddress((void**)&p_WfT,   g_WfT);

    // 1. prep (vmean, transposes, weight fold, bias fold) — q untouched
    {
        int tot = Nn * Cc / 4 + 2 * Cc * Cc + NF * Cc + NF;
        prep_kernel<<<(tot + 255) / 256, 256>>>(v, Wv, Wo, Wq, bq, Woff,
                                                boff, Wattn, battn);
    }

    // 2. vpm (fp16) = vmean @ Wv + bv
    gemm_f16<true><<<dim3(Cc / 64, Nn / 128), 256>>>(
        p_vm16, p_WvT, bv, p_vpmh, Nn, Cc);

    // 3. mega: q convert + offattn GEMM + sampling + out GEMM
    mega_kernel<<<ROWS / 32, 256>>>(q, p_WfT, p_bfold, p_WoT, bo, out);
}